// round 14
// baseline (speedup 1.0000x reference)
#include <cuda_runtime.h>
#include <cuda_fp16.h>
#include <cstdint>

#define W_g 200
#define H_g 200
#define NQ 40000
#define Dm 256
#define M_ROWS 40000

// ---------------------------------------------------------------------------
// Device scratch (no allocations allowed)
// ---------------------------------------------------------------------------
__device__ __half g_v[NQ * Dm];       // v = value @ W_v + b_v  (fp16)
__device__ float g_soaw[NQ * 192];    // cols 0..127 so, 128..191 aw (pre-softmax)
__device__ __half g_mid[NQ * Dm];     // deform output (fp16)
__device__ __half g_wv[256 * 256];    // W_v  transposed [n][k], fp16
__device__ __half g_wsa[192 * 512];   // [W_so | W_aw] transposed [n][k], fp16
__device__ __half g_wo[256 * 256];    // W_o  transposed [n][k], fp16

__device__ __forceinline__ uint32_t smem_u32(const void* p) {
    uint32_t a;
    asm("{ .reg .u64 t; cvta.to.shared.u64 t, %1; cvt.u32.u64 %0, t; }" : "=r"(a) : "l"(p));
    return a;
}
__device__ __forceinline__ void ldmatrix_x4(uint32_t* r, uint32_t addr) {
    asm volatile("ldmatrix.sync.aligned.m8n8.x4.shared.b16 {%0,%1,%2,%3}, [%4];"
                 : "=r"(r[0]), "=r"(r[1]), "=r"(r[2]), "=r"(r[3]) : "r"(addr));
}
__device__ __forceinline__ void mma_16816(float* c, const uint32_t* a, const uint32_t* b) {
    asm volatile(
        "mma.sync.aligned.m16n8k16.row.col.f32.f16.f16.f32 "
        "{%0,%1,%2,%3}, {%4,%5,%6,%7}, {%8,%9}, {%0,%1,%2,%3};"
        : "+f"(c[0]), "+f"(c[1]), "+f"(c[2]), "+f"(c[3])
        : "r"(a[0]), "r"(a[1]), "r"(a[2]), "r"(a[3]), "r"(b[0]), "r"(b[1]));
}
__device__ __forceinline__ uint32_t pack_h2(float x, float y) {
    __half2 t = __floats2half2_rn(x, y);
    return *reinterpret_cast<uint32_t*>(&t);
}
__device__ __forceinline__ void cp_async16(uint32_t dst, const void* src) {
    asm volatile("cp.async.cg.shared.global [%0], [%1], 16;" :: "r"(dst), "l"(src));
}
#define CP_COMMIT() asm volatile("cp.async.commit_group;" ::: "memory")
template <int N> __device__ __forceinline__ void cp_wait() {
    asm volatile("cp.async.wait_group %0;" :: "n"(N) : "memory");
}

// ---------------------------------------------------------------------------
// REGISTER-STAGED GEMM tile (R12-validated, for fp32 A with fused convert).
// ATYPE: 0 = fp32 A, 1 = fp32 concat ([A | A+A2], phys stride 256).
// Block 128x128, BK=32, 8 warps (2x4), warp tile 64x32; smem rows 80 B.
// ---------------------------------------------------------------------------
template <int ATYPE, bool HALF_OUT>
__device__ __forceinline__ void tile_gemm_reg(
    const float* __restrict__ Af, const float* __restrict__ A2, int ldA,
    const __half* __restrict__ B, int K, int Nb,
    const float* __restrict__ bias0, const float* __restrict__ bias1, int nsplit,
    void* __restrict__ Cv, int ldC, int bm, int bn,
    uint8_t* sA, uint8_t* sB)
{
    constexpr int TP = 128 * 80;

    const int tid  = threadIdx.x;
    const int lane = tid & 31;
    const int wid  = tid >> 5;
    const int wr   = wid >> 2;
    const int wc   = wid & 3;

    float acc[4][4][4];
    #pragma unroll
    for (int i = 0; i < 4; ++i)
        #pragma unroll
        for (int j = 0; j < 4; ++j)
            #pragma unroll
            for (int k = 0; k < 4; ++k) acc[i][j][k] = 0.f;

    const int nchunk = K >> 5;

    float4 ra[4];
    uint4  rb[2];

    auto ldg_chunk = [&](int c) {
        const int k0 = c << 5;
        #pragma unroll
        for (int i = 0; i < 4; ++i) {
            const int s = tid + i * 256;
            const int row = s >> 3, g = (s & 7) << 2;
            const int rg = min(bm + row, M_ROWS - 1);
            if (ATYPE == 0 || k0 < 256) {
                ra[i] = *(const float4*)(Af + (size_t)rg * ldA + k0 + g);
            } else {
                const int kk = k0 - 256;
                float4 p = *(const float4*)(Af + (size_t)rg * ldA + kk + g);
                float4 q = *(const float4*)(A2 + (size_t)rg * ldA + kk + g);
                ra[i] = make_float4(p.x + q.x, p.y + q.y, p.z + q.z, p.w + q.w);
            }
        }
        #pragma unroll
        for (int i = 0; i < 2; ++i) {
            const int s = tid + i * 256;
            const int row = s >> 2, g = s & 3;
            const int rg = min(bn + row, Nb - 1);
            rb[i] = *(const uint4*)(B + (size_t)rg * K + k0 + g * 8);
        }
    };

    auto sts_chunk = [&](int buf) {
        #pragma unroll
        for (int i = 0; i < 4; ++i) {
            const int s = tid + i * 256;
            const int row = s >> 3, g = (s & 7) << 2;
            uint2 hh;
            hh.x = pack_h2(ra[i].x, ra[i].y);
            hh.y = pack_h2(ra[i].z, ra[i].w);
            *(uint2*)(sA + buf * TP + row * 80 + g * 2) = hh;
        }
        #pragma unroll
        for (int i = 0; i < 2; ++i) {
            const int s = tid + i * 256;
            const int row = s >> 2, g = s & 3;
            *(uint4*)(sB + buf * TP + row * 80 + g * 16) = rb[i];
        }
    };

    const int a_r = (((lane >> 3) & 1) << 3) + (lane & 7);
    const int a_c = (lane >> 4) << 3;
    const int b_r = ((lane >> 4) << 3) + (lane & 7);
    const int b_c = ((lane >> 3) & 1) << 3;

    ldg_chunk(0);
    sts_chunk(0);
    __syncthreads();

    for (int c = 0; c < nchunk; ++c) {
        const int cur = c & 1;
        if (c + 1 < nchunk) ldg_chunk(c + 1);

        const uint32_t bA = smem_u32(sA + cur * TP);
        const uint32_t bB = smem_u32(sB + cur * TP);

        #pragma unroll
        for (int kk = 0; kk < 32; kk += 16) {
            uint32_t af[4][4];
            #pragma unroll
            for (int mc = 0; mc < 4; ++mc)
                ldmatrix_x4(af[mc], bA + (wr * 64 + mc * 16 + a_r) * 80 + (kk + a_c) * 2);
            uint32_t bf[4][2];
            #pragma unroll
            for (int jj = 0; jj < 2; ++jj) {
                uint32_t r[4];
                ldmatrix_x4(r, bB + (wc * 32 + jj * 16 + b_r) * 80 + (kk + b_c) * 2);
                bf[jj * 2 + 0][0] = r[0]; bf[jj * 2 + 0][1] = r[1];
                bf[jj * 2 + 1][0] = r[2]; bf[jj * 2 + 1][1] = r[3];
            }
            #pragma unroll
            for (int mc = 0; mc < 4; ++mc)
                #pragma unroll
                for (int ncn = 0; ncn < 4; ++ncn)
                    mma_16816(acc[mc][ncn], af[mc], bf[ncn]);
        }

        if (c + 1 < nchunk) {
            sts_chunk(1 - cur);
            __syncthreads();
        }
    }

    const int gid = lane >> 2, tig = lane & 3;
    #pragma unroll
    for (int mc = 0; mc < 4; ++mc) {
        #pragma unroll
        for (int ncn = 0; ncn < 4; ++ncn) {
            const int n0 = bn + wc * 32 + ncn * 8 + tig * 2;
            if (n0 >= Nb) continue;
            const float bx = (n0     < nsplit) ? bias0[n0]     : bias1[n0 - nsplit];
            const float by = (n0 + 1 < nsplit) ? bias0[n0 + 1] : bias1[n0 + 1 - nsplit];
            const int m0 = bm + wr * 64 + mc * 16 + gid;
            if (HALF_OUT) {
                __half* C = (__half*)Cv;
                if (m0 < M_ROWS)
                    *(__half2*)&C[(size_t)m0 * ldC + n0] =
                        __floats2half2_rn(acc[mc][ncn][0] + bx, acc[mc][ncn][1] + by);
                if (m0 + 8 < M_ROWS)
                    *(__half2*)&C[(size_t)(m0 + 8) * ldC + n0] =
                        __floats2half2_rn(acc[mc][ncn][2] + bx, acc[mc][ncn][3] + by);
            } else {
                float* C = (float*)Cv;
                if (m0 < M_ROWS)
                    *(float2*)&C[(size_t)m0 * ldC + n0] =
                        make_float2(acc[mc][ncn][0] + bx, acc[mc][ncn][1] + by);
                if (m0 + 8 < M_ROWS)
                    *(float2*)&C[(size_t)(m0 + 8) * ldC + n0] =
                        make_float2(acc[mc][ncn][2] + bx, acc[mc][ncn][3] + by);
            }
        }
    }
}

// ---------------------------------------------------------------------------
// CP.ASYNC GEMM tile (R13-validated on dense fp16 A: 3-stage pipeline, BK=32).
// ---------------------------------------------------------------------------
__device__ __forceinline__ void tile_gemm_cp(
    const __half* __restrict__ A, int ldA,
    const __half* __restrict__ B, int K, int Nb,
    const float* __restrict__ bias, float* __restrict__ C, int ldC,
    int bm, int bn, uint8_t* sA, uint8_t* sB)
{
    constexpr int TP = 128 * 80;

    const int tid  = threadIdx.x;
    const int lane = tid & 31;
    const int wid  = tid >> 5;
    const int wr   = wid >> 2;
    const int wc   = wid & 3;

    float acc[4][4][4];
    #pragma unroll
    for (int i = 0; i < 4; ++i)
        #pragma unroll
        for (int j = 0; j < 4; ++j)
            #pragma unroll
            for (int k = 0; k < 4; ++k) acc[i][j][k] = 0.f;

    const int nchunk = K >> 5;

    const uint32_t sAb = smem_u32(sA);
    const uint32_t sBb = smem_u32(sB);

    const int crow = tid >> 2;
    const int cg   = tid & 3;
    const int arow0 = min(bm + crow,      M_ROWS - 1);
    const int arow1 = min(bm + crow + 64, M_ROWS - 1);
    const int brow0 = min(bn + crow,      Nb - 1);
    const int brow1 = min(bn + crow + 64, Nb - 1);

    auto issue = [&](int c) {
        if (c < nchunk) {
            const int k0  = c << 5;
            const int buf = c % 3;
            cp_async16(sAb + buf * TP + crow * 80 + cg * 16,
                       A + (size_t)arow0 * ldA + k0 + cg * 8);
            cp_async16(sAb + buf * TP + (crow + 64) * 80 + cg * 16,
                       A + (size_t)arow1 * ldA + k0 + cg * 8);
            cp_async16(sBb + buf * TP + crow * 80 + cg * 16,
                       B + (size_t)brow0 * K + k0 + cg * 8);
            cp_async16(sBb + buf * TP + (crow + 64) * 80 + cg * 16,
                       B + (size_t)brow1 * K + k0 + cg * 8);
        }
        CP_COMMIT();
    };

    const int a_r = (((lane >> 3) & 1) << 3) + (lane & 7);
    const int a_c = (lane >> 4) << 3;
    const int b_r = ((lane >> 4) << 3) + (lane & 7);
    const int b_c = ((lane >> 3) & 1) << 3;

    issue(0);
    issue(1);

    for (int c = 0; c < nchunk; ++c) {
        cp_wait<1>();
        __syncthreads();

        const int buf = c % 3;
        const uint32_t bA = sAb + buf * TP;
        const uint32_t bB = sBb + buf * TP;

        #pragma unroll
        for (int kk = 0; kk < 32; kk += 16) {
            uint32_t af[4][4];
            #pragma unroll
            for (int mc = 0; mc < 4; ++mc)
                ldmatrix_x4(af[mc], bA + (wr * 64 + mc * 16 + a_r) * 80 + (kk + a_c) * 2);
            uint32_t bf[4][2];
            #pragma unroll
            for (int jj = 0; jj < 2; ++jj) {
                uint32_t r[4];
                ldmatrix_x4(r, bB + (wc * 32 + jj * 16 + b_r) * 80 + (kk + b_c) * 2);
                bf[jj * 2 + 0][0] = r[0]; bf[jj * 2 + 0][1] = r[1];
                bf[jj * 2 + 1][0] = r[2]; bf[jj * 2 + 1][1] = r[3];
            }
            #pragma unroll
            for (int mc = 0; mc < 4; ++mc)
                #pragma unroll
                for (int ncn = 0; ncn < 4; ++ncn)
                    mma_16816(acc[mc][ncn], af[mc], bf[ncn]);
        }

        issue(c + 2);
    }

    const int gid = lane >> 2, tig = lane & 3;
    #pragma unroll
    for (int mc = 0; mc < 4; ++mc) {
        #pragma unroll
        for (int ncn = 0; ncn < 4; ++ncn) {
            const int n0 = bn + wc * 32 + ncn * 8 + tig * 2;
            if (n0 >= Nb) continue;
            const float bx = bias[n0];
            const float by = bias[n0 + 1];
            const int m0 = bm + wr * 64 + mc * 16 + gid;
            if (m0 < M_ROWS)
                *(float2*)&C[(size_t)m0 * ldC + n0] =
                    make_float2(acc[mc][ncn][0] + bx, acc[mc][ncn][1] + by);
            if (m0 + 8 < M_ROWS)
                *(float2*)&C[(size_t)(m0 + 8) * ldC + n0] =
                    make_float2(acc[mc][ncn][2] + bx, acc[mc][ncn][3] + by);
        }
    }
}

// ---------------------------------------------------------------------------
// Fused G1+G2 (R12-validated): bx<2 -> v GEMM (A=query fp32, fp16 out),
//                              bx>=2 -> soaw GEMM (concat fp32, fp32 out).
// ---------------------------------------------------------------------------
__global__ __launch_bounds__(256) void gemm_g12(
    const float* __restrict__ query, const float* __restrict__ query_pos,
    const __half* __restrict__ wv, const __half* __restrict__ wsa,
    const float* __restrict__ b_v, const float* __restrict__ b_so,
    const float* __restrict__ b_aw,
    __half* __restrict__ gv, float* __restrict__ gsoaw)
{
    __shared__ __align__(16) uint8_t sA[2 * 128 * 80];
    __shared__ __align__(16) uint8_t sB[2 * 128 * 80];
    const int bx = blockIdx.x;
    const int bm = blockIdx.y * 128;
    if (bx < 2) {
        tile_gemm_reg<0, true>(query, nullptr, 256, wv, 256, 256,
                               b_v, b_v, 256, gv, 256, bm, bx * 128, sA, sB);
    } else {
        tile_gemm_reg<1, false>(query, query_pos, 256, wsa, 512, 192,
                                b_so, b_aw, 128, gsoaw, 192, bm, (bx - 2) * 128, sA, sB);
    }
}

// G3 (R13-validated): out = mid(fp16) @ W_o + b_o via cp.async pipeline
__global__ __launch_bounds__(256) void gemm_g3(
    const __half* __restrict__ mid, const __half* __restrict__ wo,
    const float* __restrict__ b_o, float* __restrict__ out)
{
    extern __shared__ uint8_t smem[];
    uint8_t* sA = smem;
    uint8_t* sB = smem + 3 * 128 * 80;
    tile_gemm_cp(mid, 256, wo, 256, 256, b_o, out, 256,
                 blockIdx.y * 128, blockIdx.x * 128, sA, sB);
}

// ---------------------------------------------------------------------------
// Weight transposes (R12-validated): W[k][n] fp32 -> out[n][k] fp16.
// ---------------------------------------------------------------------------
__global__ void conv_w_all(const float* __restrict__ Wv, const float* __restrict__ Wso,
                           const float* __restrict__ Waw, const float* __restrict__ Wo)
{
    const int total = 65536 + 65536 + 32768 + 65536;
    for (int i = blockIdx.x * blockDim.x + threadIdx.x; i < total;
         i += gridDim.x * blockDim.x) {
        if (i < 65536) {
            const int k = i >> 8, n = i & 255;
            g_wv[n * 256 + k] = __float2half(Wv[i]);
        } else if (i < 131072) {
            const int j = i - 65536;
            const int k = j >> 7, n = j & 127;
            g_wsa[n * 512 + k] = __float2half(Wso[j]);
        } else if (i < 163840) {
            const int j = i - 131072;
            const int k = j >> 6, n = j & 63;
            g_wsa[(128 + n) * 512 + k] = __float2half(Waw[j]);
        } else {
            const int j = i - 163840;
            const int k = j >> 8, n = j & 255;
            g_wo[n * 256 + k] = __float2half(Wo[j]);
        }
    }
}

// ---------------------------------------------------------------------------
// Deformable sampling (R10/R12-validated: half2 gathers, fp16 mid out).
// ---------------------------------------------------------------------------
__global__ __launch_bounds__(256) void deform_kernel(
    const __half* __restrict__ v, const float* __restrict__ soaw,
    const float* __restrict__ ref, __half* __restrict__ mid)
{
    __shared__ float4 s_w[64];
    __shared__ int4   s_idx[64];

    const int q   = blockIdx.x;
    const int tid = threadIdx.x;

    if (tid < 64) {
        const int h  = tid >> 3;
        const int qq = (tid >> 2) & 1;
        const int p  = tid & 3;
        const float* srow = soaw + (size_t)q * 192;

        const float rpx = ref[q * 2 + 0];
        const float rpy = ref[q * 2 + 1];

        const float sx = srow[h * 16 + qq * 8 + p * 2 + 0];
        const float sy = srow[h * 16 + qq * 8 + p * 2 + 1];
        float a        = srow[128 + h * 8 + qq * 4 + p];

        float m = fmaxf(a, __shfl_xor_sync(0xffffffffu, a, 1));
        m = fmaxf(m, __shfl_xor_sync(0xffffffffu, m, 2));
        float e = __expf(a - m);
        float s = e + __shfl_xor_sync(0xffffffffu, e, 1);
        s = s + __shfl_xor_sync(0xffffffffu, s, 2);
        const float wt = 0.5f * e / s;

        const float x = fmaf(rpx, (float)W_g, sx) - 0.5f;
        const float y = fmaf(rpy, (float)H_g, sy) - 0.5f;
        const float x0f = floorf(x), y0f = floorf(y);
        const int   x0 = (int)x0f,  y0 = (int)y0f;
        const float wx1 = x - x0f, wx0 = 1.f - wx1;
        const float wy1 = y - y0f, wy0 = 1.f - wy1;

        const bool vx0 = (x0 >= 0) && (x0 < W_g);
        const bool vx1 = (x0 + 1 >= 0) && (x0 + 1 < W_g);
        const bool vy0 = (y0 >= 0) && (y0 < H_g);
        const bool vy1 = (y0 + 1 >= 0) && (y0 + 1 < H_g);
        const int cx0 = min(max(x0, 0),     W_g - 1);
        const int cx1 = min(max(x0 + 1, 0), W_g - 1);
        const int cy0 = min(max(y0, 0),     H_g - 1);
        const int cy1 = min(max(y0 + 1, 0), H_g - 1);

        float4 w;
        w.x = wt * wx0 * wy0 * (float)(vx0 && vy0);
        w.y = wt * wx1 * wy0 * (float)(vx1 && vy0);
        w.z = wt * wx0 * wy1 * (float)(vx0 && vy1);
        w.w = wt * wx1 * wy1 * (float)(vx1 && vy1);

        int4 ix;   // byte offsets; v row = 256 half = 512 B
        ix.x = (cy0 * W_g + cx0) * 512;
        ix.y = (cy0 * W_g + cx1) * 512;
        ix.z = (cy1 * W_g + cx0) * 512;
        ix.w = (cy1 * W_g + cx1) * 512;

        s_w[tid]   = w;
        s_idx[tid] = ix;
    }
    __syncthreads();

    const int h    = tid >> 5;
    const int lane = tid & 31;
    const int sel  = lane >> 4;          // which point of the pair
    const int ch   = (lane & 15) * 2;    // channel pair
    const char* vh = (const char*)v + (size_t)(h * 32 + ch) * 2;

    float2 acc = make_float2(0.f, 0.f);
    #pragma unroll
    for (int i = 0; i < 4; ++i) {
        const int t = h * 8 + i * 2 + sel;
        const float4 w  = s_w[t];
        const int4   ix = s_idx[t];
        float2 f;
        f = __half22float2(*(const __half2*)(vh + ix.x));
        acc.x = fmaf(w.x, f.x, acc.x); acc.y = fmaf(w.x, f.y, acc.y);
        f = __half22float2(*(const __half2*)(vh + ix.y));
        acc.x = fmaf(w.y, f.x, acc.x); acc.y = fmaf(w.y, f.y, acc.y);
        f = __half22float2(*(const __half2*)(vh + ix.z));
        acc.x = fmaf(w.z, f.x, acc.x); acc.y = fmaf(w.z, f.y, acc.y);
        f = __half22float2(*(const __half2*)(vh + ix.w));
        acc.x = fmaf(w.w, f.x, acc.x); acc.y = fmaf(w.w, f.y, acc.y);
    }
    acc.x += __shfl_xor_sync(0xffffffffu, acc.x, 16);
    acc.y += __shfl_xor_sync(0xffffffffu, acc.y, 16);

    if (lane < 16)
        *(__half2*)&mid[(size_t)q * Dm + h * 32 + ch] = __floats2half2_rn(acc.x, acc.y);
}

// ---------------------------------------------------------------------------
extern "C" void kernel_launch(void* const* d_in, const int* in_sizes, int n_in,
                              void* d_out, int out_size)
{
    const float* query     = (const float*)d_in[0];
    const float* query_pos = (const float*)d_in[1];
    const float* refpts    = (const float*)d_in[2];
    const float* W_so      = (const float*)d_in[3];
    const float* b_so      = (const float*)d_in[4];
    const float* W_aw      = (const float*)d_in[5];
    const float* b_aw      = (const float*)d_in[6];
    const float* W_v       = (const float*)d_in[7];
    const float* b_v       = (const float*)d_in[8];
    const float* W_o       = (const float*)d_in[9];
    const float* b_o       = (const float*)d_in[10];
    float* out = (float*)d_out;

    __half *gv, *gmid, *wv, *wsa, *wo;
    float* gsoaw;
    cudaGetSymbolAddress((void**)&gv,    g_v);
    cudaGetSymbolAddress((void**)&gsoaw, g_soaw);
    cudaGetSymbolAddress((void**)&gmid,  g_mid);
    cudaGetSymbolAddress((void**)&wv,  g_wv);
    cudaGetSymbolAddress((void**)&wsa, g_wsa);
    cudaGetSymbolAddress((void**)&wo,  g_wo);

    constexpr int SMEM3 = 6 * 128 * 80;   // 61440 B (3 bufs A + 3 bufs B)
    cudaFuncSetAttribute(gemm_g3, cudaFuncAttributeMaxDynamicSharedMemorySize, SMEM3);

    const int gm = (M_ROWS + 127) / 128;  // 313

    conv_w_all<<<448, 512>>>(W_v, W_so, W_aw, W_o);
    gemm_g12<<<dim3(4, gm), 256>>>(query, query_pos, wv, wsa, b_v, b_so, b_aw, gv, gsoaw);
    deform_kernel<<<NQ, 256>>>(gv, gsoaw, refpts, gmid);
    gemm_g3<<<dim3(2, gm), 256, SMEM3>>>(gmid, wo, b_o, out);
}

// round 15
// speedup vs baseline: 1.5052x; 1.5052x over previous
#include <cuda_runtime.h>
#include <cuda_fp16.h>
#include <cstdint>

#define W_g 200
#define H_g 200
#define NQ 40000
#define Dm 256
#define M_ROWS 40000

// ---------------------------------------------------------------------------
// Device scratch (no allocations allowed)
// ---------------------------------------------------------------------------
__device__ __half g_v[NQ * Dm];       // v = value @ W_v + b_v  (fp16)
__device__ float g_soaw[NQ * 192];    // cols 0..127 so, 128..191 aw (pre-softmax)
__device__ __half g_mid[NQ * Dm];     // deform output (fp16)
__device__ __half g_wv[256 * 256];    // W_v  transposed [n][k], fp16
__device__ __half g_wsa[192 * 512];   // [W_so | W_aw] transposed [n][k], fp16
__device__ __half g_wo[256 * 256];    // W_o  transposed [n][k], fp16

__device__ __forceinline__ uint32_t smem_u32(const void* p) {
    uint32_t a;
    asm("{ .reg .u64 t; cvta.to.shared.u64 t, %1; cvt.u32.u64 %0, t; }" : "=r"(a) : "l"(p));
    return a;
}
__device__ __forceinline__ void ldmatrix_x4(uint32_t* r, uint32_t addr) {
    asm volatile("ldmatrix.sync.aligned.m8n8.x4.shared.b16 {%0,%1,%2,%3}, [%4];"
                 : "=r"(r[0]), "=r"(r[1]), "=r"(r[2]), "=r"(r[3]) : "r"(addr));
}
__device__ __forceinline__ void mma_16816(float* c, const uint32_t* a, const uint32_t* b) {
    asm volatile(
        "mma.sync.aligned.m16n8k16.row.col.f32.f16.f16.f32 "
        "{%0,%1,%2,%3}, {%4,%5,%6,%7}, {%8,%9}, {%0,%1,%2,%3};"
        : "+f"(c[0]), "+f"(c[1]), "+f"(c[2]), "+f"(c[3])
        : "r"(a[0]), "r"(a[1]), "r"(a[2]), "r"(a[3]), "r"(b[0]), "r"(b[1]));
}
__device__ __forceinline__ uint32_t pack_h2(float x, float y) {
    __half2 t = __floats2half2_rn(x, y);
    return *reinterpret_cast<uint32_t*>(&t);
}
__device__ __forceinline__ void cp_async16(uint32_t dst, const void* src) {
    asm volatile("cp.async.cg.shared.global [%0], [%1], 16;" :: "r"(dst), "l"(src));
}
#define CP_COMMIT() asm volatile("cp.async.commit_group;" ::: "memory")
template <int N> __device__ __forceinline__ void cp_wait() {
    asm volatile("cp.async.wait_group %0;" :: "n"(N) : "memory");
}

// ---------------------------------------------------------------------------
// REGISTER-STAGED GEMM tile (R12-validated, for fp32 A with fused convert).
// ATYPE: 0 = fp32 A, 1 = fp32 concat ([A | A+A2], phys stride 256).
// Block 128x128, BK=32, 8 warps (2x4), warp tile 64x32; smem rows 80 B.
// ---------------------------------------------------------------------------
template <int ATYPE, bool HALF_OUT>
__device__ __forceinline__ void tile_gemm_reg(
    const float* __restrict__ Af, const float* __restrict__ A2, int ldA,
    const __half* __restrict__ B, int K, int Nb,
    const float* __restrict__ bias0, const float* __restrict__ bias1, int nsplit,
    void* __restrict__ Cv, int ldC, int bm, int bn,
    uint8_t* sA, uint8_t* sB)
{
    constexpr int TP = 128 * 80;

    const int tid  = threadIdx.x;
    const int lane = tid & 31;
    const int wid  = tid >> 5;
    const int wr   = wid >> 2;
    const int wc   = wid & 3;

    float acc[4][4][4];
    #pragma unroll
    for (int i = 0; i < 4; ++i)
        #pragma unroll
        for (int j = 0; j < 4; ++j)
            #pragma unroll
            for (int k = 0; k < 4; ++k) acc[i][j][k] = 0.f;

    const int nchunk = K >> 5;

    float4 ra[4];
    uint4  rb[2];

    auto ldg_chunk = [&](int c) {
        const int k0 = c << 5;
        #pragma unroll
        for (int i = 0; i < 4; ++i) {
            const int s = tid + i * 256;
            const int row = s >> 3, g = (s & 7) << 2;
            const int rg = min(bm + row, M_ROWS - 1);
            if (ATYPE == 0 || k0 < 256) {
                ra[i] = *(const float4*)(Af + (size_t)rg * ldA + k0 + g);
            } else {
                const int kk = k0 - 256;
                float4 p = *(const float4*)(Af + (size_t)rg * ldA + kk + g);
                float4 q = *(const float4*)(A2 + (size_t)rg * ldA + kk + g);
                ra[i] = make_float4(p.x + q.x, p.y + q.y, p.z + q.z, p.w + q.w);
            }
        }
        #pragma unroll
        for (int i = 0; i < 2; ++i) {
            const int s = tid + i * 256;
            const int row = s >> 2, g = s & 3;
            const int rg = min(bn + row, Nb - 1);
            rb[i] = *(const uint4*)(B + (size_t)rg * K + k0 + g * 8);
        }
    };

    auto sts_chunk = [&](int buf) {
        #pragma unroll
        for (int i = 0; i < 4; ++i) {
            const int s = tid + i * 256;
            const int row = s >> 3, g = (s & 7) << 2;
            uint2 hh;
            hh.x = pack_h2(ra[i].x, ra[i].y);
            hh.y = pack_h2(ra[i].z, ra[i].w);
            *(uint2*)(sA + buf * TP + row * 80 + g * 2) = hh;
        }
        #pragma unroll
        for (int i = 0; i < 2; ++i) {
            const int s = tid + i * 256;
            const int row = s >> 2, g = s & 3;
            *(uint4*)(sB + buf * TP + row * 80 + g * 16) = rb[i];
        }
    };

    const int a_r = (((lane >> 3) & 1) << 3) + (lane & 7);
    const int a_c = (lane >> 4) << 3;
    const int b_r = ((lane >> 4) << 3) + (lane & 7);
    const int b_c = ((lane >> 3) & 1) << 3;

    ldg_chunk(0);
    sts_chunk(0);
    __syncthreads();

    for (int c = 0; c < nchunk; ++c) {
        const int cur = c & 1;
        if (c + 1 < nchunk) ldg_chunk(c + 1);

        const uint32_t bA = smem_u32(sA + cur * TP);
        const uint32_t bB = smem_u32(sB + cur * TP);

        #pragma unroll
        for (int kk = 0; kk < 32; kk += 16) {
            uint32_t af[4][4];
            #pragma unroll
            for (int mc = 0; mc < 4; ++mc)
                ldmatrix_x4(af[mc], bA + (wr * 64 + mc * 16 + a_r) * 80 + (kk + a_c) * 2);
            uint32_t bf[4][2];
            #pragma unroll
            for (int jj = 0; jj < 2; ++jj) {
                uint32_t r[4];
                ldmatrix_x4(r, bB + (wc * 32 + jj * 16 + b_r) * 80 + (kk + b_c) * 2);
                bf[jj * 2 + 0][0] = r[0]; bf[jj * 2 + 0][1] = r[1];
                bf[jj * 2 + 1][0] = r[2]; bf[jj * 2 + 1][1] = r[3];
            }
            #pragma unroll
            for (int mc = 0; mc < 4; ++mc)
                #pragma unroll
                for (int ncn = 0; ncn < 4; ++ncn)
                    mma_16816(acc[mc][ncn], af[mc], bf[ncn]);
        }

        if (c + 1 < nchunk) {
            sts_chunk(1 - cur);
            __syncthreads();
        }
    }

    const int gid = lane >> 2, tig = lane & 3;
    #pragma unroll
    for (int mc = 0; mc < 4; ++mc) {
        #pragma unroll
        for (int ncn = 0; ncn < 4; ++ncn) {
            const int n0 = bn + wc * 32 + ncn * 8 + tig * 2;
            if (n0 >= Nb) continue;
            const float bx = (n0     < nsplit) ? bias0[n0]     : bias1[n0 - nsplit];
            const float by = (n0 + 1 < nsplit) ? bias0[n0 + 1] : bias1[n0 + 1 - nsplit];
            const int m0 = bm + wr * 64 + mc * 16 + gid;
            if (HALF_OUT) {
                __half* C = (__half*)Cv;
                if (m0 < M_ROWS)
                    *(__half2*)&C[(size_t)m0 * ldC + n0] =
                        __floats2half2_rn(acc[mc][ncn][0] + bx, acc[mc][ncn][1] + by);
                if (m0 + 8 < M_ROWS)
                    *(__half2*)&C[(size_t)(m0 + 8) * ldC + n0] =
                        __floats2half2_rn(acc[mc][ncn][2] + bx, acc[mc][ncn][3] + by);
            } else {
                float* C = (float*)Cv;
                if (m0 < M_ROWS)
                    *(float2*)&C[(size_t)m0 * ldC + n0] =
                        make_float2(acc[mc][ncn][0] + bx, acc[mc][ncn][1] + by);
                if (m0 + 8 < M_ROWS)
                    *(float2*)&C[(size_t)(m0 + 8) * ldC + n0] =
                        make_float2(acc[mc][ncn][2] + bx, acc[mc][ncn][3] + by);
            }
        }
    }
}

// ---------------------------------------------------------------------------
// CP.ASYNC GEMM tile (validated fast in R13: 3-stage pipeline, BK=32).
// ---------------------------------------------------------------------------
__device__ __forceinline__ void tile_gemm_cp(
    const __half* __restrict__ A, int ldA,
    const __half* __restrict__ B, int K, int Nb,
    const float* __restrict__ bias, float* __restrict__ C, int ldC,
    int bm, int bn, uint8_t* sA, uint8_t* sB)
{
    constexpr int TP = 128 * 80;

    const int tid  = threadIdx.x;
    const int lane = tid & 31;
    const int wid  = tid >> 5;
    const int wr   = wid >> 2;
    const int wc   = wid & 3;

    float acc[4][4][4];
    #pragma unroll
    for (int i = 0; i < 4; ++i)
        #pragma unroll
        for (int j = 0; j < 4; ++j)
            #pragma unroll
            for (int k = 0; k < 4; ++k) acc[i][j][k] = 0.f;

    const int nchunk = K >> 5;

    const uint32_t sAb = smem_u32(sA);
    const uint32_t sBb = smem_u32(sB);

    const int crow = tid >> 2;
    const int cg   = tid & 3;
    const int arow0 = min(bm + crow,      M_ROWS - 1);
    const int arow1 = min(bm + crow + 64, M_ROWS - 1);
    const int brow0 = min(bn + crow,      Nb - 1);
    const int brow1 = min(bn + crow + 64, Nb - 1);

    auto issue = [&](int c) {
        if (c < nchunk) {
            const int k0  = c << 5;
            const int buf = c % 3;
            cp_async16(sAb + buf * TP + crow * 80 + cg * 16,
                       A + (size_t)arow0 * ldA + k0 + cg * 8);
            cp_async16(sAb + buf * TP + (crow + 64) * 80 + cg * 16,
                       A + (size_t)arow1 * ldA + k0 + cg * 8);
            cp_async16(sBb + buf * TP + crow * 80 + cg * 16,
                       B + (size_t)brow0 * K + k0 + cg * 8);
            cp_async16(sBb + buf * TP + (crow + 64) * 80 + cg * 16,
                       B + (size_t)brow1 * K + k0 + cg * 8);
        }
        CP_COMMIT();
    };

    const int a_r = (((lane >> 3) & 1) << 3) + (lane & 7);
    const int a_c = (lane >> 4) << 3;
    const int b_r = ((lane >> 4) << 3) + (lane & 7);
    const int b_c = ((lane >> 3) & 1) << 3;

    issue(0);
    issue(1);

    for (int c = 0; c < nchunk; ++c) {
        cp_wait<1>();
        __syncthreads();

        const int buf = c % 3;
        const uint32_t bA = sAb + buf * TP;
        const uint32_t bB = sBb + buf * TP;

        #pragma unroll
        for (int kk = 0; kk < 32; kk += 16) {
            uint32_t af[4][4];
            #pragma unroll
            for (int mc = 0; mc < 4; ++mc)
                ldmatrix_x4(af[mc], bA + (wr * 64 + mc * 16 + a_r) * 80 + (kk + a_c) * 2);
            uint32_t bf[4][2];
            #pragma unroll
            for (int jj = 0; jj < 2; ++jj) {
                uint32_t r[4];
                ldmatrix_x4(r, bB + (wc * 32 + jj * 16 + b_r) * 80 + (kk + b_c) * 2);
                bf[jj * 2 + 0][0] = r[0]; bf[jj * 2 + 0][1] = r[1];
                bf[jj * 2 + 1][0] = r[2]; bf[jj * 2 + 1][1] = r[3];
            }
            #pragma unroll
            for (int mc = 0; mc < 4; ++mc)
                #pragma unroll
                for (int ncn = 0; ncn < 4; ++ncn)
                    mma_16816(acc[mc][ncn], af[mc], bf[ncn]);
        }

        issue(c + 2);
    }

    const int gid = lane >> 2, tig = lane & 3;
    #pragma unroll
    for (int mc = 0; mc < 4; ++mc) {
        #pragma unroll
        for (int ncn = 0; ncn < 4; ++ncn) {
            const int n0 = bn + wc * 32 + ncn * 8 + tig * 2;
            if (n0 >= Nb) continue;
            const float bx = bias[n0];
            const float by = bias[n0 + 1];
            const int m0 = bm + wr * 64 + mc * 16 + gid;
            if (m0 < M_ROWS)
                *(float2*)&C[(size_t)m0 * ldC + n0] =
                    make_float2(acc[mc][ncn][0] + bx, acc[mc][ncn][1] + by);
            if (m0 + 8 < M_ROWS)
                *(float2*)&C[(size_t)(m0 + 8) * ldC + n0] =
                    make_float2(acc[mc][ncn][2] + bx, acc[mc][ncn][3] + by);
        }
    }
}

// ---------------------------------------------------------------------------
// Fused G1+G2 (R12-validated): bx<2 -> v GEMM (A=query fp32, fp16 out),
//                              bx>=2 -> soaw GEMM (concat fp32, fp32 out).
// ---------------------------------------------------------------------------
__global__ __launch_bounds__(256) void gemm_g12(
    const float* __restrict__ query, const float* __restrict__ query_pos,
    const __half* __restrict__ wv, const __half* __restrict__ wsa,
    const float* __restrict__ b_v, const float* __restrict__ b_so,
    const float* __restrict__ b_aw,
    __half* __restrict__ gv, float* __restrict__ gsoaw)
{
    __shared__ __align__(16) uint8_t sA[2 * 128 * 80];
    __shared__ __align__(16) uint8_t sB[2 * 128 * 80];
    const int bx = blockIdx.x;
    const int bm = blockIdx.y * 128;
    if (bx < 2) {
        tile_gemm_reg<0, true>(query, nullptr, 256, wv, 256, 256,
                               b_v, b_v, 256, gv, 256, bm, bx * 128, sA, sB);
    } else {
        tile_gemm_reg<1, false>(query, query_pos, 256, wsa, 512, 192,
                                b_so, b_aw, 128, gsoaw, 192, bm, (bx - 2) * 128, sA, sB);
    }
}

// G3: out = mid(fp16) @ W_o + b_o via cp.async pipeline
__global__ __launch_bounds__(256) void gemm_g3(
    const __half* __restrict__ mid, const __half* __restrict__ wo,
    const float* __restrict__ b_o, float* __restrict__ out)
{
    extern __shared__ uint8_t smem[];
    uint8_t* sA = smem;
    uint8_t* sB = smem + 3 * 128 * 80;
    tile_gemm_cp(mid, 256, wo, 256, 256, b_o, out, 256,
                 blockIdx.y * 128, blockIdx.x * 128, sA, sB);
}

// ---------------------------------------------------------------------------
// Weight transposes (R12-validated): W[k][n] fp32 -> out[n][k] fp16.
// ---------------------------------------------------------------------------
__global__ void conv_w_all(const float* __restrict__ Wv, const float* __restrict__ Wso,
                           const float* __restrict__ Waw, const float* __restrict__ Wo)
{
    const int total = 65536 + 65536 + 32768 + 65536;
    for (int i = blockIdx.x * blockDim.x + threadIdx.x; i < total;
         i += gridDim.x * blockDim.x) {
        if (i < 65536) {
            const int k = i >> 8, n = i & 255;
            g_wv[n * 256 + k] = __float2half(Wv[i]);
        } else if (i < 131072) {
            const int j = i - 65536;
            const int k = j >> 7, n = j & 127;
            g_wsa[n * 512 + k] = __float2half(Wso[j]);
        } else if (i < 163840) {
            const int j = i - 131072;
            const int k = j >> 6, n = j & 63;
            g_wsa[(128 + n) * 512 + k] = __float2half(Waw[j]);
        } else {
            const int j = i - 163840;
            const int k = j >> 8, n = j & 255;
            g_wo[n * 256 + k] = __float2half(Wo[j]);
        }
    }
}

// ---------------------------------------------------------------------------
// Deformable sampling (R10/R12-validated: half2 gathers, fp16 mid out).
// ---------------------------------------------------------------------------
__global__ __launch_bounds__(256) void deform_kernel(
    const __half* __restrict__ v, const float* __restrict__ soaw,
    const float* __restrict__ ref, __half* __restrict__ mid)
{
    __shared__ float4 s_w[64];
    __shared__ int4   s_idx[64];

    const int q   = blockIdx.x;
    const int tid = threadIdx.x;

    if (tid < 64) {
        const int h  = tid >> 3;
        const int qq = (tid >> 2) & 1;
        const int p  = tid & 3;
        const float* srow = soaw + (size_t)q * 192;

        const float rpx = ref[q * 2 + 0];
        const float rpy = ref[q * 2 + 1];

        const float sx = srow[h * 16 + qq * 8 + p * 2 + 0];
        const float sy = srow[h * 16 + qq * 8 + p * 2 + 1];
        float a        = srow[128 + h * 8 + qq * 4 + p];

        float m = fmaxf(a, __shfl_xor_sync(0xffffffffu, a, 1));
        m = fmaxf(m, __shfl_xor_sync(0xffffffffu, m, 2));
        float e = __expf(a - m);
        float s = e + __shfl_xor_sync(0xffffffffu, e, 1);
        s = s + __shfl_xor_sync(0xffffffffu, s, 2);
        const float wt = 0.5f * e / s;

        const float x = fmaf(rpx, (float)W_g, sx) - 0.5f;
        const float y = fmaf(rpy, (float)H_g, sy) - 0.5f;
        const float x0f = floorf(x), y0f = floorf(y);
        const int   x0 = (int)x0f,  y0 = (int)y0f;
        const float wx1 = x - x0f, wx0 = 1.f - wx1;
        const float wy1 = y - y0f, wy0 = 1.f - wy1;

        const bool vx0 = (x0 >= 0) && (x0 < W_g);
        const bool vx1 = (x0 + 1 >= 0) && (x0 + 1 < W_g);
        const bool vy0 = (y0 >= 0) && (y0 < H_g);
        const bool vy1 = (y0 + 1 >= 0) && (y0 + 1 < H_g);
        const int cx0 = min(max(x0, 0),     W_g - 1);
        const int cx1 = min(max(x0 + 1, 0), W_g - 1);
        const int cy0 = min(max(y0, 0),     H_g - 1);
        const int cy1 = min(max(y0 + 1, 0), H_g - 1);

        float4 w;
        w.x = wt * wx0 * wy0 * (float)(vx0 && vy0);
        w.y = wt * wx1 * wy0 * (float)(vx1 && vy0);
        w.z = wt * wx0 * wy1 * (float)(vx0 && vy1);
        w.w = wt * wx1 * wy1 * (float)(vx1 && vy1);

        int4 ix;   // byte offsets; v row = 256 half = 512 B
        ix.x = (cy0 * W_g + cx0) * 512;
        ix.y = (cy0 * W_g + cx1) * 512;
        ix.z = (cy1 * W_g + cx0) * 512;
        ix.w = (cy1 * W_g + cx1) * 512;

        s_w[tid]   = w;
        s_idx[tid] = ix;
    }
    __syncthreads();

    const int h    = tid >> 5;
    const int lane = tid & 31;
    const int sel  = lane >> 4;          // which point of the pair
    const int ch   = (lane & 15) * 2;    // channel pair
    const char* vh = (const char*)v + (size_t)(h * 32 + ch) * 2;

    float2 acc = make_float2(0.f, 0.f);
    #pragma unroll
    for (int i = 0; i < 4; ++i) {
        const int t = h * 8 + i * 2 + sel;
        const float4 w  = s_w[t];
        const int4   ix = s_idx[t];
        float2 f;
        f = __half22float2(*(const __half2*)(vh + ix.x));
        acc.x = fmaf(w.x, f.x, acc.x); acc.y = fmaf(w.x, f.y, acc.y);
        f = __half22float2(*(const __half2*)(vh + ix.y));
        acc.x = fmaf(w.y, f.x, acc.x); acc.y = fmaf(w.y, f.y, acc.y);
        f = __half22float2(*(const __half2*)(vh + ix.z));
        acc.x = fmaf(w.z, f.x, acc.x); acc.y = fmaf(w.z, f.y, acc.y);
        f = __half22float2(*(const __half2*)(vh + ix.w));
        acc.x = fmaf(w.w, f.x, acc.x); acc.y = fmaf(w.w, f.y, acc.y);
    }
    acc.x += __shfl_xor_sync(0xffffffffu, acc.x, 16);
    acc.y += __shfl_xor_sync(0xffffffffu, acc.y, 16);

    if (lane < 16)
        *(__half2*)&mid[(size_t)q * Dm + h * 32 + ch] = __floats2half2_rn(acc.x, acc.y);
}

// ---------------------------------------------------------------------------
extern "C" void kernel_launch(void* const* d_in, const int* in_sizes, int n_in,
                              void* d_out, int out_size)
{
    const float* query     = (const float*)d_in[0];
    const float* query_pos = (const float*)d_in[1];
    const float* refpts    = (const float*)d_in[2];
    const float* W_so      = (const float*)d_in[3];
    const float* b_so      = (const float*)d_in[4];
    const float* W_aw      = (const float*)d_in[5];
    const float* b_aw      = (const float*)d_in[6];
    const float* W_v       = (const float*)d_in[7];
    const float* b_v       = (const float*)d_in[8];
    const float* W_o       = (const float*)d_in[9];
    const float* b_o       = (const float*)d_in[10];
    float* out = (float*)d_out;

    __half *gv, *gmid, *wv, *wsa, *wo;
    float* gsoaw;
    cudaGetSymbolAddress((void**)&gv,    g_v);
    cudaGetSymbolAddress((void**)&gsoaw, g_soaw);
    cudaGetSymbolAddress((void**)&gmid,  g_mid);
    cudaGetSymbolAddress((void**)&wv,  g_wv);
    cudaGetSymbolAddress((void**)&wsa, g_wsa);
    cudaGetSymbolAddress((void**)&wo,  g_wo);

    constexpr int SMEM3 = 6 * 128 * 80;   // 61440 B (3 bufs A + 3 bufs B)
    cudaFuncSetAttribute(gemm_g3, cudaFuncAttributeMaxDynamicSharedMemorySize, SMEM3);

    const int gm = (M_ROWS + 127) / 128;  // 313

    conv_w_all<<<448, 512>>>(W_v, W_so, W_aw, W_o);
    gemm_g12<<<dim3(4, gm), 256>>>(query, query_pos, wv, wsa, b_v, b_so, b_aw, gv, gsoaw);
    deform_kernel<<<NQ, 256>>>(gv, gsoaw, refpts, gmid);
    gemm_g3<<<dim3(2, gm), 256, SMEM3>>>(gmid, wo, b_o, out);
}